// round 7
// baseline (speedup 1.0000x reference)
#include <cuda_runtime.h>
#include <cuda_bf16.h>
#include <math.h>
#include <stdint.h>

#define BB 512
#define NXD 64
#define NYD 64
#define HID 256

// ---------------- device scratch ---------------------------------------------
__device__ float    g_xp[BB * HID];        // b1 + X@W1[:64]
__device__ float    g_yp[BB * HID];        // Y@W1[64:]
__device__ uint32_t g_w2hi[HID * 128];     // W2^T hi bf16 pairs: [n][kp] kp=k/2
__device__ uint32_t g_w2lo[HID * 128];     // W2^T lo bf16 pairs
__device__ float    g_scores[BB * BB];
__device__ float    g_lse[BB];

// ---------------- helpers ----------------------------------------------------
__device__ __forceinline__ uint32_t smem_u32(const void* p) {
    uint32_t a;
    asm("{ .reg .u64 t; cvta.to.shared.u64 t, %1; cvt.u32.u64 %0, t; }"
        : "=r"(a) : "l"(p));
    return a;
}

__device__ __forceinline__ void split_pack(float v0, float v1,
                                           uint32_t& hi, uint32_t& lo) {
    __nv_bfloat162 h = __float22bfloat162_rn(make_float2(v0, v1));
    float2 hf = __bfloat1622float2(h);
    __nv_bfloat162 l = __float22bfloat162_rn(make_float2(v0 - hf.x, v1 - hf.y));
    hi = *reinterpret_cast<uint32_t*>(&h);
    lo = *reinterpret_cast<uint32_t*>(&l);
}

__device__ __forceinline__ void mma_bf16(float* c, const uint32_t* a,
                                         const uint32_t* b) {
    asm volatile(
        "mma.sync.aligned.m16n8k16.row.col.f32.bf16.bf16.f32 "
        "{%0,%1,%2,%3}, {%4,%5,%6,%7}, {%8,%9}, {%0,%1,%2,%3};"
        : "+f"(c[0]), "+f"(c[1]), "+f"(c[2]), "+f"(c[3])
        : "r"(a[0]), "r"(a[1]), "r"(a[2]), "r"(a[3]), "r"(b[0]), "r"(b[1]));
}

__device__ __forceinline__ void ldsm4(uint32_t* r, uint32_t addr) {
    asm volatile(
        "ldmatrix.sync.aligned.m8n8.x4.shared.b16 {%0,%1,%2,%3}, [%4];"
        : "=r"(r[0]), "=r"(r[1]), "=r"(r[2]), "=r"(r[3]) : "r"(addr));
}

__device__ __forceinline__ void cpa16(uint32_t dst, const void* src) {
    asm volatile("cp.async.cg.shared.global [%0], [%1], 16;"
                 :: "r"(dst), "l"(__cvta_generic_to_global(src)) : "memory");
}

// ---------------------------------------------------------------------------
// Kernel A: factorized layer-1 projections (fp32)
// ---------------------------------------------------------------------------
__global__ void proj_kernel(const float* __restrict__ X,
                            const float* __restrict__ Y,
                            const float* __restrict__ W1,
                            const float* __restrict__ b1) {
    int idx = blockIdx.x * blockDim.x + threadIdx.x;
    const int half = BB * HID;
    if (idx < half) {
        int r = idx / HID, k = idx % HID;
        float acc = b1[k];
        #pragma unroll 8
        for (int t = 0; t < NXD; t++)
            acc = fmaf(X[r * NXD + t], W1[t * HID + k], acc);
        g_xp[idx] = acc;
    } else {
        int e = idx - half;
        int r = e / HID, k = e % HID;
        float acc = 0.f;
        #pragma unroll 8
        for (int t = 0; t < NYD; t++)
            acc = fmaf(Y[r * NYD + t], W1[(NXD + t) * HID + k], acc);
        g_yp[e] = acc;
    }
}

// ---------------------------------------------------------------------------
// Kernel A2: W2^T -> packed bf16 hi/lo pairs
// ---------------------------------------------------------------------------
__global__ void prep_w2(const float* __restrict__ W2) {
    int idx = blockIdx.x * blockDim.x + threadIdx.x;  // 32768
    int n = idx >> 7, kp = idx & 127;
    float w0 = W2[(2 * kp) * HID + n];
    float w1 = W2[(2 * kp + 1) * HID + n];
    uint32_t hi, lo;
    split_pack(w0, w1, hi, lo);
    g_w2hi[idx] = hi;
    g_w2lo[idx] = lo;
}

// ---------------------------------------------------------------------------
// Kernel B: mma.sync bf16 3-split GEMM via ldmatrix + fused epilogue
// ---------------------------------------------------------------------------
#define SA   132
#define SB   20
#define A_HI 0
#define A_LO 16896
#define B_BASE 33792
#define B2S  44032
#define W3S  44288
#define PART 44544
#define SM_U32 44800
#define SM_BYTES (SM_U32 * 4)

__global__ void __launch_bounds__(256, 1)
mlp_mma_kernel(const float* __restrict__ b2,
               const float* __restrict__ W3,
               const float* __restrict__ b3) {
    extern __shared__ __align__(16) uint32_t sm[];
    const int tid = threadIdx.x;
    const int lane = tid & 31, wid = tid >> 5;
    const int lq = lane >> 2, lr = lane & 3;
    const int wm = wid >> 1, wn = wid & 1;
    const int i0 = blockIdx.y * 16, j0 = blockIdx.x * 8;
    const uint32_t sb = smem_u32(sm);

    ((float*)(sm + B2S))[tid] = b2[tid];
    ((float*)(sm + W3S))[tid] = W3[tid];

    // ---- build A = relu(xp[j]+yp[i]) split to bf16 hi/lo pairs -------------
    #pragma unroll 4
    for (int q = 0; q < 32; q++) {
        int e = tid + q * 256;
        int row = e >> 6, kp2 = e & 63;
        int i = i0 + (row >> 3), j = j0 + (row & 7);
        float4 xv = *(const float4*)(g_xp + j * HID + kp2 * 4);
        float4 yv = *(const float4*)(g_yp + i * HID + kp2 * 4);
        float v0 = fmaxf(xv.x + yv.x, 0.f), v1 = fmaxf(xv.y + yv.y, 0.f);
        float v2 = fmaxf(xv.z + yv.z, 0.f), v3 = fmaxf(xv.w + yv.w, 0.f);
        uint32_t h0, l0, h1, l1;
        split_pack(v0, v1, h0, l0);
        split_pack(v2, v3, h1, l1);
        int a = row * SA + kp2 * 2;
        sm[A_HI + a] = h0; sm[A_HI + a + 1] = h1;
        sm[A_LO + a] = l0; sm[A_LO + a + 1] = l1;
    }

    // ---- B pipeline loader --------------------------------------------------
    auto load_chunk = [&](int t, int buf) {
        int nh = t >> 3, kc = t & 7;
        uint32_t bbase = B_BASE + buf * 5120;
        #pragma unroll
        for (int q = 0; q < 4; q++) {
            int idx = tid + q * 256;
            int hl = idx >> 9;
            int nl = (idx & 511) >> 2, jj = idx & 3;
            const uint32_t* src = (hl ? g_w2lo : g_w2hi)
                                  + (nh * 128 + nl) * 128 + kc * 16 + jj * 4;
            uint32_t dst = sb + (bbase + hl * 2560 + nl * SB + jj * 4) * 4;
            cpa16(dst, src);
        }
        asm volatile("cp.async.commit_group;" ::: "memory");
    };

    load_chunk(0, 0);

    // ---- precomputed ldmatrix lane addresses (byte, smem u32 space) --------
    // A: matrices {rows m..m+7 | m+8..m+15} x {koff +0 | +16B}; lane->(row,koff)
    uint32_t aHiAddr[2], aLoAddr[2];
    {
        int arow = wm * 32 + (lane & 15);
        uint32_t koffb = (lane >> 4) ? 16u : 0u;
        #pragma unroll
        for (int mt = 0; mt < 2; mt++) {
            uint32_t base = sb + (uint32_t)((arow + mt * 16) * SA) * 4u + koffb;
            aHiAddr[mt] = base + A_HI * 4u;
            aLoAddr[mt] = base + A_LO * 4u;
        }
    }
    // B: matrices {rows n..n+7 koff0 | same rows +16B | rows n+8.. koff0 | +16B}
    uint32_t bAddr[4];
    {
        int nrow = wn * 64 + (lane & 7) + ((lane >> 4) ? 8 : 0);
        uint32_t koffb = ((lane >> 3) & 1) ? 16u : 0u;
        #pragma unroll
        for (int ntp = 0; ntp < 4; ntp++)
            bAddr[ntp] = sb + (uint32_t)(B_BASE + (nrow + ntp * 16) * SB) * 4u + koffb;
    }

    float c[2][8][4];
    #pragma unroll
    for (int mt = 0; mt < 2; mt++)
        #pragma unroll
        for (int nt = 0; nt < 8; nt++)
            #pragma unroll
            for (int q = 0; q < 4; q++) c[mt][nt][q] = 0.f;

    float pr[2][2] = {{0.f, 0.f}, {0.f, 0.f}};
    const float* b2s = (const float*)(sm + B2S);
    const float* w3s = (const float*)(sm + W3S);

    for (int t = 0; t < 16; t++) {
        const int buf = t & 1;
        const int nh = t >> 3, kc = t & 7;
        if (t < 15) {
            load_chunk(t + 1, buf ^ 1);
            asm volatile("cp.async.wait_group 1;" ::: "memory");
        } else {
            asm volatile("cp.async.wait_group 0;" ::: "memory");
        }
        __syncthreads();

        const uint32_t bufOff = (uint32_t)buf * 5120u * 4u;

        #pragma unroll
        for (int s = 0; s < 2; s++) {
            const uint32_t akb = (uint32_t)(kc * 16 + s * 8) * 4u;
            const uint32_t bkb = bufOff + (uint32_t)s * 32u;

            uint32_t ah[2][4], al[2][4];
            #pragma unroll
            for (int mt = 0; mt < 2; mt++) {
                ldsm4(ah[mt], aHiAddr[mt] + akb);
                ldsm4(al[mt], aLoAddr[mt] + akb);
            }
            #pragma unroll
            for (int ntp = 0; ntp < 4; ntp++) {
                uint32_t bh[4], bl[4];
                ldsm4(bh, bAddr[ntp] + bkb);
                ldsm4(bl, bAddr[ntp] + bkb + 2560u * 4u);
                #pragma unroll
                for (int g = 0; g < 2; g++) {
                    int nt = ntp * 2 + g;
                    #pragma unroll
                    for (int mt = 0; mt < 2; mt++) {
                        mma_bf16(c[mt][nt], ah[mt], bh + g * 2);
                        mma_bf16(c[mt][nt], ah[mt], bl + g * 2);
                        mma_bf16(c[mt][nt], al[mt], bh + g * 2);
                    }
                }
            }
        }

        if (kc == 7) {                       // N-half done -> partial epilogue
            #pragma unroll
            for (int mt = 0; mt < 2; mt++)
                #pragma unroll
                for (int nt = 0; nt < 8; nt++)
                    #pragma unroll
                    for (int q = 0; q < 4; q++) {
                        int col = nh * 128 + wn * 64 + nt * 8 + lr * 2 + (q & 1);
                        float h = fmaxf(c[mt][nt][q] + b2s[col], 0.f);
                        pr[mt][q >> 1] = fmaf(h, w3s[col], pr[mt][q >> 1]);
                        c[mt][nt][q] = 0.f;
                    }
        }
        __syncthreads();
    }

    // ---- reduce partial dots over lane%4 group, combine warps --------------
    #pragma unroll
    for (int mt = 0; mt < 2; mt++)
        #pragma unroll
        for (int rh = 0; rh < 2; rh++) {
            float p = pr[mt][rh];
            p += __shfl_xor_sync(0xffffffffu, p, 1);
            p += __shfl_xor_sync(0xffffffffu, p, 2);
            if (lr == 0) {
                int row = wm * 32 + mt * 16 + rh * 8 + lq;
                ((float*)(sm + PART))[row * 2 + wn] = p;
            }
        }
    __syncthreads();

    if (tid < 128) {
        const float* part = (const float*)(sm + PART);
        float sc = part[tid * 2] + part[tid * 2 + 1] + b3[0];
        int i = i0 + (tid >> 3), j = j0 + (tid & 7);
        g_scores[i * BB + j] = sc;
    }
}

// ---------------------------------------------------------------------------
// Kernel C1: per-row logsumexp
// ---------------------------------------------------------------------------
__global__ void lse_kernel() {
    __shared__ float red[256];
    const int row = blockIdx.x;
    const int tid = threadIdx.x;
    const float* s = g_scores + row * BB;

    float mx = -INFINITY;
    for (int cc = tid; cc < BB; cc += 256) mx = fmaxf(mx, s[cc]);
    red[tid] = mx;
    __syncthreads();
    for (int o = 128; o; o >>= 1) {
        if (tid < o) red[tid] = fmaxf(red[tid], red[tid + o]);
        __syncthreads();
    }
    mx = red[0];
    __syncthreads();

    float sum = 0.f;
    for (int cc = tid; cc < BB; cc += 256) sum += expf(s[cc] - mx);
    red[tid] = sum;
    __syncthreads();
    for (int o = 128; o; o >>= 1) {
        if (tid < o) red[tid] += red[tid + o];
        __syncthreads();
    }
    if (tid == 0) g_lse[row] = mx + logf(red[0]);
}

// ---------------------------------------------------------------------------
// Kernel C2: final scalar
// ---------------------------------------------------------------------------
__global__ void final_kernel(float* __restrict__ out) {
    __shared__ float rd[512];
    __shared__ float rl[512];
    const int t = threadIdx.x;
    rd[t] = g_scores[t * BB + t];
    rl[t] = g_lse[t];
    __syncthreads();
    for (int o = 256; o; o >>= 1) {
        if (t < o) { rd[t] += rd[t + o]; rl[t] += rl[t + o]; }
        __syncthreads();
    }
    if (t == 0) {
        float mi = logf((float)BB) + rd[0] / (float)BB - rl[0] / (float)BB;
        out[0] = -mi;
    }
}

// ---------------------------------------------------------------------------
extern "C" void kernel_launch(void* const* d_in, const int* in_sizes, int n_in,
                              void* d_out, int out_size) {
    const float* dataX = (const float*)d_in[0];
    const float* dataY = (const float*)d_in[1];
    const float* W1    = (const float*)d_in[2];
    const float* b1    = (const float*)d_in[3];
    const float* W2    = (const float*)d_in[4];
    const float* b2    = (const float*)d_in[5];
    const float* W3    = (const float*)d_in[6];
    const float* b3    = (const float*)d_in[7];
    float* out = (float*)d_out;

    cudaFuncSetAttribute(mlp_mma_kernel,
                         cudaFuncAttributeMaxDynamicSharedMemorySize, SM_BYTES);

    proj_kernel<<<(2 * BB * HID) / 256, 256>>>(dataX, dataY, W1, b1);
    prep_w2<<<(HID * 128) / 256, 256>>>(W2);

    dim3 grid(BB / 8, BB / 16);   // 64 x-tiles x 32 y-tiles
    mlp_mma_kernel<<<grid, 256, SM_BYTES>>>(b2, W3, b3);

    lse_kernel<<<BB, 256>>>();
    final_kernel<<<1, BB>>>(out);
}

// round 8
// speedup vs baseline: 1.3773x; 1.3773x over previous
#include <cuda_runtime.h>
#include <cuda_fp16.h>
#include <math.h>
#include <stdint.h>

#define BB 512
#define NXD 64
#define NYD 64
#define HID 256

// ---------------- device scratch ---------------------------------------------
__device__ float    g_xp[BB * HID];        // b1 + X@W1[:64]
__device__ float    g_yp[BB * HID];        // Y@W1[64:]
__device__ uint32_t g_w2h[HID * 128];      // W2^T fp16 pairs: [n][kp], kp=k/2
__device__ float    g_scores[BB * BB];
__device__ float    g_lse[BB];

// ---------------- helpers ----------------------------------------------------
__device__ __forceinline__ uint32_t smem_u32(const void* p) {
    uint32_t a;
    asm("{ .reg .u64 t; cvta.to.shared.u64 t, %1; cvt.u32.u64 %0, t; }"
        : "=r"(a) : "l"(p));
    return a;
}

__device__ __forceinline__ void split_pack_h(float v0, float v1,
                                             uint32_t& hi, uint32_t& lo) {
    __half2 h = __float22half2_rn(make_float2(v0, v1));
    float2 hf = __half22float2(h);
    __half2 l = __float22half2_rn(make_float2(v0 - hf.x, v1 - hf.y));
    hi = *reinterpret_cast<uint32_t*>(&h);
    lo = *reinterpret_cast<uint32_t*>(&l);
}

__device__ __forceinline__ void mma_f16(float* c, const uint32_t* a,
                                        const uint32_t* b) {
    asm volatile(
        "mma.sync.aligned.m16n8k16.row.col.f32.f16.f16.f32 "
        "{%0,%1,%2,%3}, {%4,%5,%6,%7}, {%8,%9}, {%0,%1,%2,%3};"
        : "+f"(c[0]), "+f"(c[1]), "+f"(c[2]), "+f"(c[3])
        : "r"(a[0]), "r"(a[1]), "r"(a[2]), "r"(a[3]), "r"(b[0]), "r"(b[1]));
}

__device__ __forceinline__ void ldsm4(uint32_t* r, uint32_t addr) {
    asm volatile(
        "ldmatrix.sync.aligned.m8n8.x4.shared.b16 {%0,%1,%2,%3}, [%4];"
        : "=r"(r[0]), "=r"(r[1]), "=r"(r[2]), "=r"(r[3]) : "r"(addr));
}

__device__ __forceinline__ void cpa16(uint32_t dst, const void* src) {
    asm volatile("cp.async.cg.shared.global [%0], [%1], 16;"
                 :: "r"(dst), "l"(__cvta_generic_to_global(src)) : "memory");
}

// ---------------------------------------------------------------------------
// Kernel A: factorized layer-1 projections (fp32)
// ---------------------------------------------------------------------------
__global__ void proj_kernel(const float* __restrict__ X,
                            const float* __restrict__ Y,
                            const float* __restrict__ W1,
                            const float* __restrict__ b1) {
    int idx = blockIdx.x * blockDim.x + threadIdx.x;
    const int half = BB * HID;
    if (idx < half) {
        int r = idx / HID, k = idx % HID;
        float acc = b1[k];
        #pragma unroll 8
        for (int t = 0; t < NXD; t++)
            acc = fmaf(X[r * NXD + t], W1[t * HID + k], acc);
        g_xp[idx] = acc;
    } else {
        int e = idx - half;
        int r = e / HID, k = e % HID;
        float acc = 0.f;
        #pragma unroll 8
        for (int t = 0; t < NYD; t++)
            acc = fmaf(Y[r * NYD + t], W1[(NXD + t) * HID + k], acc);
        g_yp[e] = acc;
    }
}

// ---------------------------------------------------------------------------
// Kernel A2: W2^T -> packed fp16 pairs. g_w2h[n*128+kp] = pack(W2[2kp][n], W2[2kp+1][n])
// ---------------------------------------------------------------------------
__global__ void prep_w2(const float* __restrict__ W2) {
    int idx = blockIdx.x * blockDim.x + threadIdx.x;  // 32768
    int n = idx >> 7, kp = idx & 127;
    float w0 = W2[(2 * kp) * HID + n];
    float w1 = W2[(2 * kp + 1) * HID + n];
    __half2 h = __float22half2_rn(make_float2(w0, w1));
    g_w2h[idx] = *reinterpret_cast<uint32_t*>(&h);
}

// ---------------------------------------------------------------------------
// Kernel B: mma.sync fp16 (A 2-split, B single) GEMM + fused epilogue.
// CTA: 128 pairs (16 y x 8 x), N=256 in two halves of 128, K=256.
// smem (uint32 units):
//   A_HI [0,16896)      128 rows x 128 kp fp16x2, stride 132
//   A_LO [16896,33792)
//   B    [33792,38912)  2 bufs x 2560, 128 cols x 16 kp, stride 20
//   B2S  [38912,39168)  W3S [39168,39424)  PART [39424,39680)
// ---------------------------------------------------------------------------
#define SA   132
#define SB   20
#define A_HI 0
#define A_LO 16896
#define B_BASE 33792
#define B2S  38912
#define W3S  39168
#define PART 39424
#define SM_U32 39680
#define SM_BYTES (SM_U32 * 4)

__global__ void __launch_bounds__(256, 1)
mlp_mma_kernel(const float* __restrict__ b2,
               const float* __restrict__ W3,
               const float* __restrict__ b3) {
    extern __shared__ __align__(16) uint32_t sm[];
    const int tid = threadIdx.x;
    const int lane = tid & 31, wid = tid >> 5;
    const int lq = lane >> 2, lr = lane & 3;
    const int wm = wid >> 1, wn = wid & 1;
    const int i0 = blockIdx.y * 16, j0 = blockIdx.x * 8;
    const uint32_t sb = smem_u32(sm);

    ((float*)(sm + B2S))[tid] = b2[tid];
    ((float*)(sm + W3S))[tid] = W3[tid];

    // ---- build A = relu(xp[j]+yp[i]) split to fp16 hi/lo pairs -------------
    #pragma unroll 4
    for (int q = 0; q < 32; q++) {
        int e = tid + q * 256;
        int row = e >> 6, kp2 = e & 63;
        int i = i0 + (row >> 3), j = j0 + (row & 7);
        float4 xv = *(const float4*)(g_xp + j * HID + kp2 * 4);
        float4 yv = *(const float4*)(g_yp + i * HID + kp2 * 4);
        float v0 = fmaxf(xv.x + yv.x, 0.f), v1 = fmaxf(xv.y + yv.y, 0.f);
        float v2 = fmaxf(xv.z + yv.z, 0.f), v3 = fmaxf(xv.w + yv.w, 0.f);
        uint32_t h0, l0, h1, l1;
        split_pack_h(v0, v1, h0, l0);
        split_pack_h(v2, v3, h1, l1);
        int a = row * SA + kp2 * 2;
        sm[A_HI + a] = h0; sm[A_HI + a + 1] = h1;
        sm[A_LO + a] = l0; sm[A_LO + a + 1] = l1;
    }

    // ---- B pipeline loader: 16 chunks (nh 0..1 x kc 0..7), 10KB each -------
    auto load_chunk = [&](int t, int buf) {
        int nh = t >> 3, kc = t & 7;
        uint32_t bbase = B_BASE + buf * 2560;
        #pragma unroll
        for (int q = 0; q < 2; q++) {
            int idx = tid + q * 256;        // 512 float4: [n_local][jj]
            int nl = idx >> 2, jj = idx & 3;
            const uint32_t* src = g_w2h + (nh * 128 + nl) * 128 + kc * 16 + jj * 4;
            uint32_t dst = sb + (bbase + nl * SB + jj * 4) * 4;
            cpa16(dst, src);
        }
        asm volatile("cp.async.commit_group;" ::: "memory");
    };

    load_chunk(0, 0);

    // ---- precomputed ldmatrix lane addresses -------------------------------
    uint32_t aHiAddr[2], aLoAddr[2];
    {
        int arow = wm * 32 + (lane & 15);
        uint32_t koffb = (lane >> 4) ? 16u : 0u;
        #pragma unroll
        for (int mt = 0; mt < 2; mt++) {
            uint32_t base = sb + (uint32_t)((arow + mt * 16) * SA) * 4u + koffb;
            aHiAddr[mt] = base + A_HI * 4u;
            aLoAddr[mt] = base + A_LO * 4u;
        }
    }
    uint32_t bAddr[4];
    {
        int nrow = wn * 64 + (lane & 7) + ((lane >> 4) ? 8 : 0);
        uint32_t koffb = ((lane >> 3) & 1) ? 16u : 0u;
        #pragma unroll
        for (int ntp = 0; ntp < 4; ntp++)
            bAddr[ntp] = sb + (uint32_t)(B_BASE + (nrow + ntp * 16) * SB) * 4u + koffb;
    }

    float c[2][8][4];
    #pragma unroll
    for (int mt = 0; mt < 2; mt++)
        #pragma unroll
        for (int nt = 0; nt < 8; nt++)
            #pragma unroll
            for (int q = 0; q < 4; q++) c[mt][nt][q] = 0.f;

    float pr[2][2] = {{0.f, 0.f}, {0.f, 0.f}};
    const float* b2s = (const float*)(sm + B2S);
    const float* w3s = (const float*)(sm + W3S);

    for (int t = 0; t < 16; t++) {
        const int buf = t & 1;
        const int nh = t >> 3, kc = t & 7;
        if (t < 15) {
            load_chunk(t + 1, buf ^ 1);
            asm volatile("cp.async.wait_group 1;" ::: "memory");
        } else {
            asm volatile("cp.async.wait_group 0;" ::: "memory");
        }
        __syncthreads();

        const uint32_t bufOff = (uint32_t)buf * 2560u * 4u;

        #pragma unroll
        for (int s = 0; s < 2; s++) {
            const uint32_t akb = (uint32_t)(kc * 16 + s * 8) * 4u;
            const uint32_t bkb = bufOff + (uint32_t)s * 32u;

            uint32_t ah[2][4], al[2][4];
            #pragma unroll
            for (int mt = 0; mt < 2; mt++) {
                ldsm4(ah[mt], aHiAddr[mt] + akb);
                ldsm4(al[mt], aLoAddr[mt] + akb);
            }
            #pragma unroll
            for (int ntp = 0; ntp < 4; ntp++) {
                uint32_t bh[4];
                ldsm4(bh, bAddr[ntp] + bkb);
                #pragma unroll
                for (int g = 0; g < 2; g++) {
                    int nt = ntp * 2 + g;
                    #pragma unroll
                    for (int mt = 0; mt < 2; mt++) {
                        mma_f16(c[mt][nt], ah[mt], bh + g * 2);
                        mma_f16(c[mt][nt], al[mt], bh + g * 2);
                    }
                }
            }
        }

        if (kc == 7) {                       // N-half done -> partial epilogue
            #pragma unroll
            for (int mt = 0; mt < 2; mt++)
                #pragma unroll
                for (int nt = 0; nt < 8; nt++)
                    #pragma unroll
                    for (int q = 0; q < 4; q++) {
                        int col = nh * 128 + wn * 64 + nt * 8 + lr * 2 + (q & 1);
                        float h = fmaxf(c[mt][nt][q] + b2s[col], 0.f);
                        pr[mt][q >> 1] = fmaf(h, w3s[col], pr[mt][q >> 1]);
                        c[mt][nt][q] = 0.f;
                    }
        }
        __syncthreads();
    }

    // ---- reduce partial dots over lane%4 group, combine warps --------------
    #pragma unroll
    for (int mt = 0; mt < 2; mt++)
        #pragma unroll
        for (int rh = 0; rh < 2; rh++) {
            float p = pr[mt][rh];
            p += __shfl_xor_sync(0xffffffffu, p, 1);
            p += __shfl_xor_sync(0xffffffffu, p, 2);
            if (lr == 0) {
                int row = wm * 32 + mt * 16 + rh * 8 + lq;
                ((float*)(sm + PART))[row * 2 + wn] = p;
            }
        }
    __syncthreads();

    if (tid < 128) {
        const float* part = (const float*)(sm + PART);
        float sc = part[tid * 2] + part[tid * 2 + 1] + b3[0];
        int i = i0 + (tid >> 3), j = j0 + (tid & 7);
        g_scores[i * BB + j] = sc;
    }
}

// ---------------------------------------------------------------------------
// Kernel C1: per-row logsumexp
// ---------------------------------------------------------------------------
__global__ void lse_kernel() {
    __shared__ float red[256];
    const int row = blockIdx.x;
    const int tid = threadIdx.x;
    const float* s = g_scores + row * BB;

    float mx = -INFINITY;
    for (int cc = tid; cc < BB; cc += 256) mx = fmaxf(mx, s[cc]);
    red[tid] = mx;
    __syncthreads();
    for (int o = 128; o; o >>= 1) {
        if (tid < o) red[tid] = fmaxf(red[tid], red[tid + o]);
        __syncthreads();
    }
    mx = red[0];
    __syncthreads();

    float sum = 0.f;
    for (int cc = tid; cc < BB; cc += 256) sum += expf(s[cc] - mx);
    red[tid] = sum;
    __syncthreads();
    for (int o = 128; o; o >>= 1) {
        if (tid < o) red[tid] += red[tid + o];
        __syncthreads();
    }
    if (tid == 0) g_lse[row] = mx + logf(red[0]);
}

// ---------------------------------------------------------------------------
// Kernel C2: final scalar
// ---------------------------------------------------------------------------
__global__ void final_kernel(float* __restrict__ out) {
    __shared__ float rd[512];
    __shared__ float rl[512];
    const int t = threadIdx.x;
    rd[t] = g_scores[t * BB + t];
    rl[t] = g_lse[t];
    __syncthreads();
    for (int o = 256; o; o >>= 1) {
        if (t < o) { rd[t] += rd[t + o]; rl[t] += rl[t + o]; }
        __syncthreads();
    }
    if (t == 0) {
        float mi = logf((float)BB) + rd[0] / (float)BB - rl[0] / (float)BB;
        out[0] = -mi;
    }
}

// ---------------------------------------------------------------------------
extern "C" void kernel_launch(void* const* d_in, const int* in_sizes, int n_in,
                              void* d_out, int out_size) {
    const float* dataX = (const float*)d_in[0];
    const float* dataY = (const float*)d_in[1];
    const float* W1    = (const float*)d_in[2];
    const float* b1    = (const float*)d_in[3];
    const float* W2    = (const float*)d_in[4];
    const float* b2    = (const float*)d_in[5];
    const float* W3    = (const float*)d_in[6];
    const float* b3    = (const float*)d_in[7];
    float* out = (float*)d_out;

    cudaFuncSetAttribute(mlp_mma_kernel,
                         cudaFuncAttributeMaxDynamicSharedMemorySize, SM_BYTES);

    proj_kernel<<<(2 * BB * HID) / 256, 256>>>(dataX, dataY, W1, b1);
    prep_w2<<<(HID * 128) / 256, 256>>>(W2);

    dim3 grid(BB / 8, BB / 16);   // 64 x-tiles x 32 y-tiles
    mlp_mma_kernel<<<grid, 256, SM_BYTES>>>(b2, W3, b3);

    lse_kernel<<<BB, 256>>>();
    final_kernel<<<1, BB>>>(out);
}

// round 9
// speedup vs baseline: 2.6065x; 1.8925x over previous
#include <cuda_runtime.h>
#include <cuda_fp16.h>
#include <math.h>
#include <stdint.h>

#define BB 512
#define NXD 64
#define NYD 64
#define HID 256

// ---------------- device scratch ---------------------------------------------
__device__ float    g_xp[BB * HID];        // b1 + X@W1[:64]
__device__ float    g_yp[BB * HID];        // Y@W1[64:]
__device__ uint32_t g_w2h[HID * 128];      // W2^T fp16 pairs: [n][kp], kp=k/2
__device__ float    g_scores[BB * BB];
__device__ float    g_lse[BB];

// ---------------- helpers ----------------------------------------------------
__device__ __forceinline__ uint32_t smem_u32(const void* p) {
    uint32_t a;
    asm("{ .reg .u64 t; cvta.to.shared.u64 t, %1; cvt.u32.u64 %0, t; }"
        : "=r"(a) : "l"(p));
    return a;
}

__device__ __forceinline__ void mma_f16(float* c, const uint32_t* a,
                                        const uint32_t* b) {
    asm volatile(
        "mma.sync.aligned.m16n8k16.row.col.f32.f16.f16.f32 "
        "{%0,%1,%2,%3}, {%4,%5,%6,%7}, {%8,%9}, {%0,%1,%2,%3};"
        : "+f"(c[0]), "+f"(c[1]), "+f"(c[2]), "+f"(c[3])
        : "r"(a[0]), "r"(a[1]), "r"(a[2]), "r"(a[3]), "r"(b[0]), "r"(b[1]));
}

__device__ __forceinline__ void ldsm4(uint32_t* r, uint32_t addr) {
    asm volatile(
        "ldmatrix.sync.aligned.m8n8.x4.shared.b16 {%0,%1,%2,%3}, [%4];"
        : "=r"(r[0]), "=r"(r[1]), "=r"(r[2]), "=r"(r[3]) : "r"(addr));
}

__device__ __forceinline__ void cpa16(uint32_t dst, const void* src) {
    asm volatile("cp.async.cg.shared.global [%0], [%1], 16;"
                 :: "r"(dst), "l"(__cvta_generic_to_global(src)) : "memory");
}

// ---------------------------------------------------------------------------
// Kernel A: factorized layer-1 projections (fp32)
// ---------------------------------------------------------------------------
__global__ void proj_kernel(const float* __restrict__ X,
                            const float* __restrict__ Y,
                            const float* __restrict__ W1,
                            const float* __restrict__ b1) {
    int idx = blockIdx.x * blockDim.x + threadIdx.x;
    const int half = BB * HID;
    if (idx < half) {
        int r = idx / HID, k = idx % HID;
        float acc = b1[k];
        #pragma unroll 8
        for (int t = 0; t < NXD; t++)
            acc = fmaf(X[r * NXD + t], W1[t * HID + k], acc);
        g_xp[idx] = acc;
    } else {
        int e = idx - half;
        int r = e / HID, k = e % HID;
        float acc = 0.f;
        #pragma unroll 8
        for (int t = 0; t < NYD; t++)
            acc = fmaf(Y[r * NYD + t], W1[(NXD + t) * HID + k], acc);
        g_yp[e] = acc;
    }
}

// ---------------------------------------------------------------------------
// Kernel A2: W2^T -> packed fp16 pairs. g_w2h[n*128+kp] = pack(W2[2kp][n], W2[2kp+1][n])
// ---------------------------------------------------------------------------
__global__ void prep_w2(const float* __restrict__ W2) {
    int idx = blockIdx.x * blockDim.x + threadIdx.x;  // 32768
    int n = idx >> 7, kp = idx & 127;
    float w0 = W2[(2 * kp) * HID + n];
    float w1 = W2[(2 * kp + 1) * HID + n];
    __half2 h = __float22half2_rn(make_float2(w0, w1));
    g_w2h[idx] = *reinterpret_cast<uint32_t*>(&h);
}

// ---------------------------------------------------------------------------
// Kernel B: mma.sync fp16 single-term GEMM + fused epilogue, occupancy 2.
// CTA: 128 pairs (16 y x 8 x), N=256 in two halves of 128, K=256.
// smem (uint32 units):
//   A    [0,16896)      128 rows x 128 kp fp16x2, stride 132
//   B    [16896,22016)  2 bufs x 2560, 128 cols x 16 kp, stride 20
//   B2S  [22016,22272)  W3S [22272,22528)  PART [22528,22784)
// ---------------------------------------------------------------------------
#define SA   132
#define SB   20
#define A_HI 0
#define B_BASE 16896
#define B2S  22016
#define W3S  22272
#define PART 22528
#define SM_U32 22784
#define SM_BYTES (SM_U32 * 4)

__global__ void __launch_bounds__(256, 2)
mlp_mma_kernel(const float* __restrict__ b2,
               const float* __restrict__ W3,
               const float* __restrict__ b3) {
    extern __shared__ __align__(16) uint32_t sm[];
    const int tid = threadIdx.x;
    const int lane = tid & 31, wid = tid >> 5;
    const int lq = lane >> 2, lr = lane & 3;
    const int wm = wid >> 1, wn = wid & 1;
    const int i0 = blockIdx.y * 16, j0 = blockIdx.x * 8;
    const uint32_t sb = smem_u32(sm);

    ((float*)(sm + B2S))[tid] = b2[tid];
    ((float*)(sm + W3S))[tid] = W3[tid];

    // ---- build A = relu(xp[j]+yp[i]) as fp16 pairs -------------------------
    #pragma unroll 4
    for (int q = 0; q < 32; q++) {
        int e = tid + q * 256;
        int row = e >> 6, kp2 = e & 63;
        int i = i0 + (row >> 3), j = j0 + (row & 7);
        float4 xv = *(const float4*)(g_xp + j * HID + kp2 * 4);
        float4 yv = *(const float4*)(g_yp + i * HID + kp2 * 4);
        __half2 h0 = __float22half2_rn(make_float2(fmaxf(xv.x + yv.x, 0.f),
                                                   fmaxf(xv.y + yv.y, 0.f)));
        __half2 h1 = __float22half2_rn(make_float2(fmaxf(xv.z + yv.z, 0.f),
                                                   fmaxf(xv.w + yv.w, 0.f)));
        int a = row * SA + kp2 * 2;
        sm[A_HI + a]     = *reinterpret_cast<uint32_t*>(&h0);
        sm[A_HI + a + 1] = *reinterpret_cast<uint32_t*>(&h1);
    }

    // ---- B pipeline loader: 16 chunks (nh 0..1 x kc 0..7), 10KB each -------
    auto load_chunk = [&](int t, int buf) {
        int nh = t >> 3, kc = t & 7;
        uint32_t bbase = B_BASE + buf * 2560;
        #pragma unroll
        for (int q = 0; q < 2; q++) {
            int idx = tid + q * 256;        // 512 float4: [n_local][jj]
            int nl = idx >> 2, jj = idx & 3;
            const uint32_t* src = g_w2h + (nh * 128 + nl) * 128 + kc * 16 + jj * 4;
            uint32_t dst = sb + (bbase + nl * SB + jj * 4) * 4;
            cpa16(dst, src);
        }
        asm volatile("cp.async.commit_group;" ::: "memory");
    };

    load_chunk(0, 0);

    // ---- precomputed ldmatrix lane addresses -------------------------------
    uint32_t aAddr[2];
    {
        int arow = wm * 32 + (lane & 15);
        uint32_t koffb = (lane >> 4) ? 16u : 0u;
        #pragma unroll
        for (int mt = 0; mt < 2; mt++)
            aAddr[mt] = sb + (uint32_t)((A_HI + (arow + mt * 16) * SA)) * 4u + koffb;
    }
    uint32_t bAddr[4];
    {
        int nrow = wn * 64 + (lane & 7) + ((lane >> 4) ? 8 : 0);
        uint32_t koffb = ((lane >> 3) & 1) ? 16u : 0u;
        #pragma unroll
        for (int ntp = 0; ntp < 4; ntp++)
            bAddr[ntp] = sb + (uint32_t)(B_BASE + (nrow + ntp * 16) * SB) * 4u + koffb;
    }

    float c[2][8][4];
    #pragma unroll
    for (int mt = 0; mt < 2; mt++)
        #pragma unroll
        for (int nt = 0; nt < 8; nt++)
            #pragma unroll
            for (int q = 0; q < 4; q++) c[mt][nt][q] = 0.f;

    float pr[2][2] = {{0.f, 0.f}, {0.f, 0.f}};
    const float* b2s = (const float*)(sm + B2S);
    const float* w3s = (const float*)(sm + W3S);

    for (int t = 0; t < 16; t++) {
        const int buf = t & 1;
        const int nh = t >> 3, kc = t & 7;
        if (t < 15) {
            load_chunk(t + 1, buf ^ 1);
            asm volatile("cp.async.wait_group 1;" ::: "memory");
        } else {
            asm volatile("cp.async.wait_group 0;" ::: "memory");
        }
        __syncthreads();

        const uint32_t bufOff = (uint32_t)buf * 2560u * 4u;

        #pragma unroll
        for (int s = 0; s < 2; s++) {
            const uint32_t akb = (uint32_t)(kc * 16 + s * 8) * 4u;
            const uint32_t bkb = bufOff + (uint32_t)s * 32u;

            uint32_t ah[2][4];
            ldsm4(ah[0], aAddr[0] + akb);
            ldsm4(ah[1], aAddr[1] + akb);
            #pragma unroll
            for (int ntp = 0; ntp < 4; ntp++) {
                uint32_t bh[4];
                ldsm4(bh, bAddr[ntp] + bkb);
                #pragma unroll
                for (int g = 0; g < 2; g++) {
                    int nt = ntp * 2 + g;
                    mma_f16(c[0][nt], ah[0], bh + g * 2);
                    mma_f16(c[1][nt], ah[1], bh + g * 2);
                }
            }
        }

        if (kc == 7) {                       // N-half done -> partial epilogue
            #pragma unroll
            for (int mt = 0; mt < 2; mt++)
                #pragma unroll
                for (int nt = 0; nt < 8; nt++)
                    #pragma unroll
                    for (int q = 0; q < 4; q++) {
                        int col = nh * 128 + wn * 64 + nt * 8 + lr * 2 + (q & 1);
                        float h = fmaxf(c[mt][nt][q] + b2s[col], 0.f);
                        pr[mt][q >> 1] = fmaf(h, w3s[col], pr[mt][q >> 1]);
                        c[mt][nt][q] = 0.f;
                    }
        }
        __syncthreads();
    }

    // ---- reduce partial dots over lane%4 group, combine warps --------------
    #pragma unroll
    for (int mt = 0; mt < 2; mt++)
        #pragma unroll
        for (int rh = 0; rh < 2; rh++) {
            float p = pr[mt][rh];
            p += __shfl_xor_sync(0xffffffffu, p, 1);
            p += __shfl_xor_sync(0xffffffffu, p, 2);
            if (lr == 0) {
                int row = wm * 32 + mt * 16 + rh * 8 + lq;
                ((float*)(sm + PART))[row * 2 + wn] = p;
            }
        }
    __syncthreads();

    if (tid < 128) {
        const float* part = (const float*)(sm + PART);
        float sc = part[tid * 2] + part[tid * 2 + 1] + b3[0];
        int i = i0 + (tid >> 3), j = j0 + (tid & 7);
        g_scores[i * BB + j] = sc;
    }
}

// ---------------------------------------------------------------------------
// Kernel C1: per-row logsumexp
// ---------------------------------------------------------------------------
__global__ void lse_kernel() {
    __shared__ float red[256];
    const int row = blockIdx.x;
    const int tid = threadIdx.x;
    const float* s = g_scores + row * BB;

    float mx = -INFINITY;
    for (int cc = tid; cc < BB; cc += 256) mx = fmaxf(mx, s[cc]);
    red[tid] = mx;
    __syncthreads();
    for (int o = 128; o; o >>= 1) {
        if (tid < o) red[tid] = fmaxf(red[tid], red[tid + o]);
        __syncthreads();
    }
    mx = red[0];
    __syncthreads();

    float sum = 0.f;
    for (int cc = tid; cc < BB; cc += 256) sum += expf(s[cc] - mx);
    red[tid] = sum;
    __syncthreads();
    for (int o = 128; o; o >>= 1) {
        if (tid < o) red[tid] += red[tid + o];
        __syncthreads();
    }
    if (tid == 0) g_lse[row] = mx + logf(red[0]);
}

// ---------------------------------------------------------------------------
// Kernel C2: final scalar
// ---------------------------------------------------------------------------
__global__ void final_kernel(float* __restrict__ out) {
    __shared__ float rd[512];
    __shared__ float rl[512];
    const int t = threadIdx.x;
    rd[t] = g_scores[t * BB + t];
    rl[t] = g_lse[t];
    __syncthreads();
    for (int o = 256; o; o >>= 1) {
        if (t < o) { rd[t] += rd[t + o]; rl[t] += rl[t + o]; }
        __syncthreads();
    }
    if (t == 0) {
        float mi = logf((float)BB) + rd[0] / (float)BB - rl[0] / (float)BB;
        out[0] = -mi;
    }
}

// ---------------------------------------------------------------------------
extern "C" void kernel_launch(void* const* d_in, const int* in_sizes, int n_in,
                              void* d_out, int out_size) {
    const float* dataX = (const float*)d_in[0];
    const float* dataY = (const float*)d_in[1];
    const float* W1    = (const float*)d_in[2];
    const float* b1    = (const float*)d_in[3];
    const float* W2    = (const float*)d_in[4];
    const float* b2    = (const float*)d_in[5];
    const float* W3    = (const float*)d_in[6];
    const float* b3    = (const float*)d_in[7];
    float* out = (float*)d_out;

    cudaFuncSetAttribute(mlp_mma_kernel,
                         cudaFuncAttributeMaxDynamicSharedMemorySize, SM_BYTES);

    proj_kernel<<<(2 * BB * HID) / 256, 256>>>(dataX, dataY, W1, b1);
    prep_w2<<<(HID * 128) / 256, 256>>>(W2);

    dim3 grid(BB / 8, BB / 16);   // 64 x-tiles x 32 y-tiles
    mlp_mma_kernel<<<grid, 256, SM_BYTES>>>(b2, W3, b3);

    lse_kernel<<<BB, 256>>>();
    final_kernel<<<1, BB>>>(out);
}

// round 10
// speedup vs baseline: 2.8534x; 1.0947x over previous
#include <cuda_runtime.h>
#include <cuda_fp16.h>
#include <math.h>
#include <stdint.h>

#define BB 512
#define NXD 64
#define NYD 64
#define HID 256

// ---------------- device scratch ---------------------------------------------
__device__ __align__(16) uint32_t g_xph[BB * 128];   // fp16 pairs: b1 + X@W1[:64]
__device__ __align__(16) uint32_t g_yph[BB * 128];   // fp16 pairs: Y@W1[64:]
__device__ __align__(16) uint32_t g_w2h[HID * 128];  // W2^T fp16 pairs [n][kp]
__device__ float g_rowpart[64 * BB];                  // per (bx, i) sum of exp(score)
__device__ float g_diag[BB];

// ---------------- helpers ----------------------------------------------------
__device__ __forceinline__ uint32_t smem_u32(const void* p) {
    uint32_t a;
    asm("{ .reg .u64 t; cvta.to.shared.u64 t, %1; cvt.u32.u64 %0, t; }"
        : "=r"(a) : "l"(p));
    return a;
}

__device__ __forceinline__ void mma_f16(float* c, const uint32_t* a,
                                        const uint32_t* b) {
    asm volatile(
        "mma.sync.aligned.m16n8k16.row.col.f32.f16.f16.f32 "
        "{%0,%1,%2,%3}, {%4,%5,%6,%7}, {%8,%9}, {%0,%1,%2,%3};"
        : "+f"(c[0]), "+f"(c[1]), "+f"(c[2]), "+f"(c[3])
        : "r"(a[0]), "r"(a[1]), "r"(a[2]), "r"(a[3]), "r"(b[0]), "r"(b[1]));
}

__device__ __forceinline__ void ldsm4(uint32_t* r, uint32_t addr) {
    asm volatile(
        "ldmatrix.sync.aligned.m8n8.x4.shared.b16 {%0,%1,%2,%3}, [%4];"
        : "=r"(r[0]), "=r"(r[1]), "=r"(r[2]), "=r"(r[3]) : "r"(addr));
}

__device__ __forceinline__ void cpa16(uint32_t dst, const void* src) {
    asm volatile("cp.async.cg.shared.global [%0], [%1], 16;"
                 :: "r"(dst), "l"(__cvta_generic_to_global(src)) : "memory");
}

// ---------------------------------------------------------------------------
// Kernel A: factorized layer-1 projections -> fp16 pairs
// ---------------------------------------------------------------------------
__global__ void proj_kernel(const float* __restrict__ X,
                            const float* __restrict__ Y,
                            const float* __restrict__ W1,
                            const float* __restrict__ b1) {
    int idx = blockIdx.x * blockDim.x + threadIdx.x;   // 2 * 512 * 128
    const int half = BB * 128;
    if (idx < half) {
        int r = idx >> 7, kp = idx & 127;
        float a0 = b1[2 * kp], a1 = b1[2 * kp + 1];
        #pragma unroll 8
        for (int t = 0; t < NXD; t++) {
            float xv = X[r * NXD + t];
            a0 = fmaf(xv, W1[t * HID + 2 * kp], a0);
            a1 = fmaf(xv, W1[t * HID + 2 * kp + 1], a1);
        }
        __half2 h = __float22half2_rn(make_float2(a0, a1));
        g_xph[idx] = *reinterpret_cast<uint32_t*>(&h);
    } else {
        int e = idx - half;
        int r = e >> 7, kp = e & 127;
        float a0 = 0.f, a1 = 0.f;
        #pragma unroll 8
        for (int t = 0; t < NYD; t++) {
            float yv = Y[r * NYD + t];
            a0 = fmaf(yv, W1[(NXD + t) * HID + 2 * kp], a0);
            a1 = fmaf(yv, W1[(NXD + t) * HID + 2 * kp + 1], a1);
        }
        __half2 h = __float22half2_rn(make_float2(a0, a1));
        g_yph[e] = *reinterpret_cast<uint32_t*>(&h);
    }
}

// ---------------------------------------------------------------------------
// Kernel A2: W2^T -> packed fp16 pairs
// ---------------------------------------------------------------------------
__global__ void prep_w2(const float* __restrict__ W2) {
    int idx = blockIdx.x * blockDim.x + threadIdx.x;  // 32768
    int n = idx >> 7, kp = idx & 127;
    float w0 = W2[(2 * kp) * HID + n];
    float w1 = W2[(2 * kp + 1) * HID + n];
    __half2 h = __float22half2_rn(make_float2(w0, w1));
    g_w2h[idx] = *reinterpret_cast<uint32_t*>(&h);
}

// ---------------------------------------------------------------------------
// Kernel B: mma.sync fp16 GEMM + fused epilogue + fused exp row-partials.
// CTA: 128 pairs (16 y x 8 x), N=256 in two halves of 128, K=256. occ 2.
// smem (u32): A [0,16896) stride 132 | B [16896,22016) 2x2560 stride 20
//             B2S [22016) W3S [22272) PART [22528) ; total 22784 u32
// ---------------------------------------------------------------------------
#define SA   132
#define SB   20
#define A_HI 0
#define B_BASE 16896
#define B2S  22016
#define W3S  22272
#define PART 22528
#define SM_U32 22784
#define SM_BYTES (SM_U32 * 4)

__global__ void __launch_bounds__(256, 2)
mlp_mma_kernel(const float* __restrict__ b2,
               const float* __restrict__ W3,
               const float* __restrict__ b3) {
    extern __shared__ __align__(16) uint32_t sm[];
    const int tid = threadIdx.x;
    const int lane = tid & 31, wid = tid >> 5;
    const int lq = lane >> 2, lr = lane & 3;
    const int wm = wid >> 1, wn = wid & 1;
    const int i0 = blockIdx.y * 16, j0 = blockIdx.x * 8;
    const uint32_t sb = smem_u32(sm);

    ((float*)(sm + B2S))[tid] = b2[tid];
    ((float*)(sm + W3S))[tid] = W3[tid];

    // ---- build A = relu(xph[j]+yph[i]) in half2, uint4 granularity ---------
    const __half2 z2 = __float2half2_rn(0.f);
    #pragma unroll
    for (int q = 0; q < 16; q++) {
        int e = tid + q * 256;              // uint4 index: (row, c4) c4 in 0..31
        int row = e >> 5, c4 = e & 31;
        int i = i0 + (row >> 3), j = j0 + (row & 7);
        uint4 xv = *(const uint4*)(g_xph + j * 128 + c4 * 4);
        uint4 yv = *(const uint4*)(g_yph + i * 128 + c4 * 4);
        uint4 o;
        __half2 t0, t1, t2, t3;
        t0 = __hmax2(__hadd2(*(__half2*)&xv.x, *(__half2*)&yv.x), z2);
        t1 = __hmax2(__hadd2(*(__half2*)&xv.y, *(__half2*)&yv.y), z2);
        t2 = __hmax2(__hadd2(*(__half2*)&xv.z, *(__half2*)&yv.z), z2);
        t3 = __hmax2(__hadd2(*(__half2*)&xv.w, *(__half2*)&yv.w), z2);
        o.x = *(uint32_t*)&t0; o.y = *(uint32_t*)&t1;
        o.z = *(uint32_t*)&t2; o.w = *(uint32_t*)&t3;
        *(uint4*)(sm + A_HI + row * SA + c4 * 4) = o;
    }

    // ---- B pipeline loader: 16 chunks (nh 0..1 x kc 0..7), 10KB each -------
    auto load_chunk = [&](int t, int buf) {
        int nh = t >> 3, kc = t & 7;
        uint32_t bbase = B_BASE + buf * 2560;
        #pragma unroll
        for (int q = 0; q < 2; q++) {
            int idx = tid + q * 256;        // 512 float4: [n_local][jj]
            int nl = idx >> 2, jj = idx & 3;
            const uint32_t* src = g_w2h + (nh * 128 + nl) * 128 + kc * 16 + jj * 4;
            uint32_t dst = sb + (bbase + nl * SB + jj * 4) * 4;
            cpa16(dst, src);
        }
        asm volatile("cp.async.commit_group;" ::: "memory");
    };

    load_chunk(0, 0);

    // ---- precomputed ldmatrix lane addresses -------------------------------
    uint32_t aAddr[2];
    {
        int arow = wm * 32 + (lane & 15);
        uint32_t koffb = (lane >> 4) ? 16u : 0u;
        #pragma unroll
        for (int mt = 0; mt < 2; mt++)
            aAddr[mt] = sb + (uint32_t)((A_HI + (arow + mt * 16) * SA)) * 4u + koffb;
    }
    uint32_t bAddr[4];
    {
        int nrow = wn * 64 + (lane & 7) + ((lane >> 4) ? 8 : 0);
        uint32_t koffb = ((lane >> 3) & 1) ? 16u : 0u;
        #pragma unroll
        for (int ntp = 0; ntp < 4; ntp++)
            bAddr[ntp] = sb + (uint32_t)(B_BASE + (nrow + ntp * 16) * SB) * 4u + koffb;
    }

    float c[2][8][4];
    #pragma unroll
    for (int mt = 0; mt < 2; mt++)
        #pragma unroll
        for (int nt = 0; nt < 8; nt++)
            #pragma unroll
            for (int q = 0; q < 4; q++) c[mt][nt][q] = 0.f;

    float pr[2][2] = {{0.f, 0.f}, {0.f, 0.f}};
    const float* b2s = (const float*)(sm + B2S);
    const float* w3s = (const float*)(sm + W3S);

    for (int t = 0; t < 16; t++) {
        const int buf = t & 1;
        const int nh = t >> 3, kc = t & 7;
        if (t < 15) {
            load_chunk(t + 1, buf ^ 1);
            asm volatile("cp.async.wait_group 1;" ::: "memory");
        } else {
            asm volatile("cp.async.wait_group 0;" ::: "memory");
        }
        __syncthreads();

        const uint32_t bufOff = (uint32_t)buf * 2560u * 4u;

        #pragma unroll
        for (int s = 0; s < 2; s++) {
            const uint32_t akb = (uint32_t)(kc * 16 + s * 8) * 4u;
            const uint32_t bkb = bufOff + (uint32_t)s * 32u;

            uint32_t ah[2][4];
            ldsm4(ah[0], aAddr[0] + akb);
            ldsm4(ah[1], aAddr[1] + akb);
            #pragma unroll
            for (int ntp = 0; ntp < 4; ntp++) {
                uint32_t bh[4];
                ldsm4(bh, bAddr[ntp] + bkb);
                #pragma unroll
                for (int g = 0; g < 2; g++) {
                    int nt = ntp * 2 + g;
                    mma_f16(c[0][nt], ah[0], bh + g * 2);
                    mma_f16(c[1][nt], ah[1], bh + g * 2);
                }
            }
        }

        if (kc == 7) {                       // N-half done -> partial epilogue
            #pragma unroll
            for (int mt = 0; mt < 2; mt++)
                #pragma unroll
                for (int nt = 0; nt < 8; nt++)
                    #pragma unroll
                    for (int q = 0; q < 4; q++) {
                        int col = nh * 128 + wn * 64 + nt * 8 + lr * 2 + (q & 1);
                        float h = fmaxf(c[mt][nt][q] + b2s[col], 0.f);
                        pr[mt][q >> 1] = fmaf(h, w3s[col], pr[mt][q >> 1]);
                        c[mt][nt][q] = 0.f;
                    }
        }
        __syncthreads();
    }

    // ---- reduce partial dots over lane%4 group, combine warps --------------
    #pragma unroll
    for (int mt = 0; mt < 2; mt++)
        #pragma unroll
        for (int rh = 0; rh < 2; rh++) {
            float p = pr[mt][rh];
            p += __shfl_xor_sync(0xffffffffu, p, 1);
            p += __shfl_xor_sync(0xffffffffu, p, 2);
            if (lr == 0) {
                int row = wm * 32 + mt * 16 + rh * 8 + lq;
                ((float*)(sm + PART))[row * 2 + wn] = p;
            }
        }
    __syncthreads();

    // ---- scores -> fused exp row-partials + diag ---------------------------
    if (tid < 128) {                          // warps 0-3, fully active
        const float* part = (const float*)(sm + PART);
        float sc = part[tid * 2] + part[tid * 2 + 1] + b3[0];
        int i = i0 + (tid >> 3), j = j0 + (tid & 7);
        if (i == j) g_diag[i] = sc;
        float e = expf(sc);                   // scores are O(1): no max shift
        e += __shfl_xor_sync(0xffffffffu, e, 1);
        e += __shfl_xor_sync(0xffffffffu, e, 2);
        e += __shfl_xor_sync(0xffffffffu, e, 4);
        if ((tid & 7) == 0)
            g_rowpart[blockIdx.x * BB + i] = e;
    }
}

// ---------------------------------------------------------------------------
// Kernel C: final scalar (reduce 64 partials/row -> lse, then means)
// ---------------------------------------------------------------------------
__global__ void final_kernel(float* __restrict__ out) {
    __shared__ float rd[512];
    __shared__ float rl[512];
    const int t = threadIdx.x;                // 512
    float s = 0.f;
    #pragma unroll 8
    for (int bx = 0; bx < 64; bx++)           // coalesced: stride BB across bx
        s += g_rowpart[bx * BB + t];
    rl[t] = logf(s);
    rd[t] = g_diag[t];
    __syncthreads();
    for (int o = 256; o; o >>= 1) {
        if (t < o) { rd[t] += rd[t + o]; rl[t] += rl[t + o]; }
        __syncthreads();
    }
    if (t == 0) {
        float mi = logf((float)BB) + rd[0] / (float)BB - rl[0] / (float)BB;
        out[0] = -mi;
    }
}

// ---------------------------------------------------------------------------
extern "C" void kernel_launch(void* const* d_in, const int* in_sizes, int n_in,
                              void* d_out, int out_size) {
    const float* dataX = (const float*)d_in[0];
    const float* dataY = (const float*)d_in[1];
    const float* W1    = (const float*)d_in[2];
    const float* b1    = (const float*)d_in[3];
    const float* W2    = (const float*)d_in[4];
    const float* b2    = (const float*)d_in[5];
    const float* W3    = (const float*)d_in[6];
    const float* b3    = (const float*)d_in[7];
    float* out = (float*)d_out;

    cudaFuncSetAttribute(mlp_mma_kernel,
                         cudaFuncAttributeMaxDynamicSharedMemorySize, SM_BYTES);

    proj_kernel<<<(2 * BB * 128) / 256, 256>>>(dataX, dataY, W1, b1);
    prep_w2<<<(HID * 128) / 256, 256>>>(W2);

    dim3 grid(BB / 8, BB / 16);   // 64 x-tiles x 32 y-tiles
    mlp_mma_kernel<<<grid, 256, SM_BYTES>>>(b2, W3, b3);

    final_kernel<<<1, BB>>>(out);
}

// round 12
// speedup vs baseline: 3.0968x; 1.0853x over previous
#include <cuda_runtime.h>
#include <cuda_fp16.h>
#include <math.h>
#include <stdint.h>

#define BB 512
#define NXD 64
#define NYD 64
#define HID 256

// ---------------- device scratch ---------------------------------------------
__device__ __align__(16) uint32_t g_xph[BB * 128];   // fp16 pairs: b1 + X@W1[:64]
__device__ __align__(16) uint32_t g_yph[BB * 128];   // fp16 pairs: Y@W1[64:]
__device__ __align__(16) uint32_t g_w2h[HID * 128];  // W2^T fp16 pairs [n][kp]
__device__ __align__(16) float g_rowpart[BB * 64];   // [row i][bx] sum of exp
__device__ float g_diag[BB];

// ---------------- helpers ----------------------------------------------------
__device__ __forceinline__ uint32_t smem_u32(const void* p) {
    uint32_t a;
    asm("{ .reg .u64 t; cvta.to.shared.u64 t, %1; cvt.u32.u64 %0, t; }"
        : "=r"(a) : "l"(p));
    return a;
}

__device__ __forceinline__ void mma_f16(float* c, const uint32_t* a,
                                        const uint32_t* b) {
    asm volatile(
        "mma.sync.aligned.m16n8k16.row.col.f32.f16.f16.f32 "
        "{%0,%1,%2,%3}, {%4,%5,%6,%7}, {%8,%9}, {%0,%1,%2,%3};"
        : "+f"(c[0]), "+f"(c[1]), "+f"(c[2]), "+f"(c[3])
        : "r"(a[0]), "r"(a[1]), "r"(a[2]), "r"(a[3]), "r"(b[0]), "r"(b[1]));
}

__device__ __forceinline__ void ldsm4(uint32_t* r, uint32_t addr) {
    asm volatile(
        "ldmatrix.sync.aligned.m8n8.x4.shared.b16 {%0,%1,%2,%3}, [%4];"
        : "=r"(r[0]), "=r"(r[1]), "=r"(r[2]), "=r"(r[3]) : "r"(addr));
}

__device__ __forceinline__ void cpa16(uint32_t dst, const void* src) {
    asm volatile("cp.async.cg.shared.global [%0], [%1], 16;"
                 :: "r"(dst), "l"(__cvta_generic_to_global(src)) : "memory");
}

// ---------------------------------------------------------------------------
// Kernel A: fused prep — projections to fp16 + W2^T fp16 pack
// grid covers 3 ranges: xp (65536), yp (65536), w2 (32768)
// ---------------------------------------------------------------------------
__global__ void prep_all(const float* __restrict__ X,
                         const float* __restrict__ Y,
                         const float* __restrict__ W1,
                         const float* __restrict__ b1,
                         const float* __restrict__ W2) {
    int idx = blockIdx.x * blockDim.x + threadIdx.x;
    const int half = BB * 128;
    if (idx < half) {
        int r = idx >> 7, kp = idx & 127;
        float a0 = b1[2 * kp], a1 = b1[2 * kp + 1];
        #pragma unroll 8
        for (int t = 0; t < NXD; t++) {
            float xv = X[r * NXD + t];
            a0 = fmaf(xv, W1[t * HID + 2 * kp], a0);
            a1 = fmaf(xv, W1[t * HID + 2 * kp + 1], a1);
        }
        __half2 h = __float22half2_rn(make_float2(a0, a1));
        g_xph[idx] = *reinterpret_cast<uint32_t*>(&h);
    } else if (idx < 2 * half) {
        int e = idx - half;
        int r = e >> 7, kp = e & 127;
        float a0 = 0.f, a1 = 0.f;
        #pragma unroll 8
        for (int t = 0; t < NYD; t++) {
            float yv = Y[r * NYD + t];
            a0 = fmaf(yv, W1[(NXD + t) * HID + 2 * kp], a0);
            a1 = fmaf(yv, W1[(NXD + t) * HID + 2 * kp + 1], a1);
        }
        __half2 h = __float22half2_rn(make_float2(a0, a1));
        g_yph[e] = *reinterpret_cast<uint32_t*>(&h);
    } else {
        int e = idx - 2 * half;                 // 32768
        int n = e >> 7, kp = e & 127;
        float w0 = W2[(2 * kp) * HID + n];
        float w1 = W2[(2 * kp + 1) * HID + n];
        __half2 h = __float22half2_rn(make_float2(w0, w1));
        g_w2h[e] = *reinterpret_cast<uint32_t*>(&h);
    }
}

// ---------------------------------------------------------------------------
// Kernel B: mma.sync fp16 GEMM + fused epilogue + fused exp row-partials.
// CTA: 128 pairs (16 y x 8 x), N=256 in two halves, K=256 in 4 chunks of 64.
// smem (u32): A [0,16896) stride 132 | B [16896,26112) 2 bufs x 4608 stride 36
//             B2S [26112) W3S [26368) PART [26624) ; total 26880 u32 (107.5KB)
// ---------------------------------------------------------------------------
#define SA   132
#define SB   36
#define A_HI 0
#define B_BASE 16896
#define B2S  26112
#define W3S  26368
#define PART 26624
#define SM_U32 26880
#define SM_BYTES (SM_U32 * 4)

__global__ void __launch_bounds__(256, 2)
mlp_mma_kernel(const float* __restrict__ b2,
               const float* __restrict__ W3,
               const float* __restrict__ b3) {
    extern __shared__ __align__(16) uint32_t sm[];
    const int tid = threadIdx.x;
    const int lane = tid & 31, wid = tid >> 5;
    const int lq = lane >> 2, lr = lane & 3;
    const int wm = wid >> 1, wn = wid & 1;
    const int i0 = blockIdx.y * 16, j0 = blockIdx.x * 8;
    const uint32_t sb = smem_u32(sm);

    ((float*)(sm + B2S))[tid] = b2[tid];
    ((float*)(sm + W3S))[tid] = W3[tid];

    // ---- build A = relu(xph[j]+yph[i]) in half2, uint4 granularity ---------
    const __half2 z2 = __float2half2_rn(0.f);
    #pragma unroll
    for (int q = 0; q < 16; q++) {
        int e = tid + q * 256;              // uint4 index: (row, c4) c4 in 0..31
        int row = e >> 5, c4 = e & 31;
        int i = i0 + (row >> 3), j = j0 + (row & 7);
        uint4 xv = *(const uint4*)(g_xph + j * 128 + c4 * 4);
        uint4 yv = *(const uint4*)(g_yph + i * 128 + c4 * 4);
        uint4 o;
        __half2 t0, t1, t2, t3;
        t0 = __hmax2(__hadd2(*(__half2*)&xv.x, *(__half2*)&yv.x), z2);
        t1 = __hmax2(__hadd2(*(__half2*)&xv.y, *(__half2*)&yv.y), z2);
        t2 = __hmax2(__hadd2(*(__half2*)&xv.z, *(__half2*)&yv.z), z2);
        t3 = __hmax2(__hadd2(*(__half2*)&xv.w, *(__half2*)&yv.w), z2);
        o.x = *(uint32_t*)&t0; o.y = *(uint32_t*)&t1;
        o.z = *(uint32_t*)&t2; o.w = *(uint32_t*)&t3;
        *(uint4*)(sm + A_HI + row * SA + c4 * 4) = o;
    }

    // ---- B pipeline: 8 chunks (nh 0..1 x kc 0..3), K=64 each (18KB) --------
    auto load_chunk = [&](int t, int buf) {
        int nh = t >> 2, kc = t & 3;
        uint32_t bbase = B_BASE + buf * 4608;
        #pragma unroll
        for (int q = 0; q < 4; q++) {
            int idx = tid + q * 256;        // 1024 float4: [nl (128)][jj (8)]
            int nl = idx >> 3, jj = idx & 7;
            const uint32_t* src = g_w2h + (nh * 128 + nl) * 128 + kc * 32 + jj * 4;
            uint32_t dst = sb + (bbase + nl * SB + jj * 4) * 4;
            cpa16(dst, src);
        }
        asm volatile("cp.async.commit_group;" ::: "memory");
    };

    load_chunk(0, 0);

    // ---- precomputed ldmatrix lane addresses -------------------------------
    uint32_t aAddr[2];
    {
        int arow = wm * 32 + (lane & 15);
        uint32_t koffb = (lane >> 4) ? 16u : 0u;
        #pragma unroll
        for (int mt = 0; mt < 2; mt++)
            aAddr[mt] = sb + (uint32_t)((A_HI + (arow + mt * 16) * SA)) * 4u + koffb;
    }
    uint32_t bAddr[4];
    {
        int nrow = wn * 64 + (lane & 7) + ((lane >> 4) ? 8 : 0);
        uint32_t koffb = ((lane >> 3) & 1) ? 16u : 0u;
        #pragma unroll
        for (int ntp = 0; ntp < 4; ntp++)
            bAddr[ntp] = sb + (uint32_t)(B_BASE + (nrow + ntp * 16) * SB) * 4u + koffb;
    }

    float c[2][8][4];
    #pragma unroll
    for (int mt = 0; mt < 2; mt++)
        #pragma unroll
        for (int nt = 0; nt < 8; nt++)
            #pragma unroll
            for (int q = 0; q < 4; q++) c[mt][nt][q] = 0.f;

    float pr[2][2] = {{0.f, 0.f}, {0.f, 0.f}};
    const float* b2s = (const float*)(sm + B2S);
    const float* w3s = (const float*)(sm + W3S);

    for (int t = 0; t < 8; t++) {
        const int buf = t & 1;
        const int nh = t >> 2, kc = t & 3;
        if (t < 7) {
            load_chunk(t + 1, buf ^ 1);
            asm volatile("cp.async.wait_group 1;" ::: "memory");
        } else {
            asm volatile("cp.async.wait_group 0;" ::: "memory");
        }
        __syncthreads();

        const uint32_t bufOff = (uint32_t)buf * 4608u * 4u;

        #pragma unroll
        for (int s = 0; s < 4; s++) {
            const uint32_t akb = (uint32_t)(kc * 32 + s * 8) * 4u;
            const uint32_t bkb = bufOff + (uint32_t)s * 32u;

            uint32_t ah[2][4];
            ldsm4(ah[0], aAddr[0] + akb);
            ldsm4(ah[1], aAddr[1] + akb);
            #pragma unroll
            for (int ntp = 0; ntp < 4; ntp++) {
                uint32_t bh[4];
                ldsm4(bh, bAddr[ntp] + bkb);
                #pragma unroll
                for (int g = 0; g < 2; g++) {
                    int nt = ntp * 2 + g;
                    mma_f16(c[0][nt], ah[0], bh + g * 2);
                    mma_f16(c[1][nt], ah[1], bh + g * 2);
                }
            }
        }

        if (kc == 3) {                       // N-half done -> partial epilogue
            #pragma unroll
            for (int mt = 0; mt < 2; mt++)
                #pragma unroll
                for (int nt = 0; nt < 8; nt++)
                    #pragma unroll
                    for (int q = 0; q < 4; q++) {
                        int col = nh * 128 + wn * 64 + nt * 8 + lr * 2 + (q & 1);
                        float h = fmaxf(c[mt][nt][q] + b2s[col], 0.f);
                        pr[mt][q >> 1] = fmaf(h, w3s[col], pr[mt][q >> 1]);
                        c[mt][nt][q] = 0.f;
                    }
        }
        __syncthreads();
    }

    // ---- reduce partial dots over lane%4 group, combine warps --------------
    #pragma unroll
    for (int mt = 0; mt < 2; mt++)
        #pragma unroll
        for (int rh = 0; rh < 2; rh++) {
            float p = pr[mt][rh];
            p += __shfl_xor_sync(0xffffffffu, p, 1);
            p += __shfl_xor_sync(0xffffffffu, p, 2);
            if (lr == 0) {
                int row = wm * 32 + mt * 16 + rh * 8 + lq;
                ((float*)(sm + PART))[row * 2 + wn] = p;
            }
        }
    __syncthreads();

    // ---- scores -> fused exp row-partials + diag ---------------------------
    if (tid < 128) {                          // warps 0-3, fully active
        const float* part = (const float*)(sm + PART);
        float sc = part[tid * 2] + part[tid * 2 + 1] + b3[0];
        int i = i0 + (tid >> 3), j = j0 + (tid & 7);
        if (i == j) g_diag[i] = sc;
        float e = expf(sc);                   // scores are O(1): no max shift
        e += __shfl_xor_sync(0xffffffffu, e, 1);
        e += __shfl_xor_sync(0xffffffffu, e, 2);
        e += __shfl_xor_sync(0xffffffffu, e, 4);
        if ((tid & 7) == 0)
            g_rowpart[i * 64 + blockIdx.x] = e;   // transposed: row-major
    }
}

// ---------------------------------------------------------------------------
// Kernel C: final scalar — vectorized row reduce (MLP 16), then tree
// ---------------------------------------------------------------------------
__global__ void final_kernel(float* __restrict__ out) {
    __shared__ float rd[512];
    __shared__ float rl[512];
    const int t = threadIdx.x;                // 512
    const float4* rp = (const float4*)(g_rowpart + t * 64);
    float s0 = 0.f, s1 = 0.f, s2 = 0.f, s3 = 0.f;
    #pragma unroll
    for (int q = 0; q < 16; q++) {
        float4 v = rp[q];
        s0 += v.x; s1 += v.y; s2 += v.z; s3 += v.w;
    }
    rl[t] = logf((s0 + s1) + (s2 + s3));
    rd[t] = g_diag[t];
    __syncthreads();
    for (int o = 256; o; o >>= 1) {
        if (t < o) { rd[t] += rd[t + o]; rl[t] += rl[t + o]; }
        __syncthreads();
    }
    if (t == 0) {
        float mi = logf((float)BB) + rd[0] / (float)BB - rl[0] / (float)BB;
        out[0] = -mi;
    }
}

// ---------------------------------------------------------------------------
extern "C" void kernel_launch(void* const* d_in, const int* in_sizes, int n_in,
                              void* d_out, int out_size) {
    const float* dataX = (const float*)d_in[0];
    const float* dataY = (const float*)d_in[1];
    const float* W1    = (const float*)d_in[2];
    const float* b1    = (const float*)d_in[3];
    const float* W2    = (const float*)d_in[4];
    const float* b2    = (const float*)d_in[5];
    const float* W3    = (const float*)d_in[6];
    const float* b3    = (const float*)d_in[7];
    float* out = (float*)d_out;

    cudaFuncSetAttribute(mlp_mma_kernel,
                         cudaFuncAttributeMaxDynamicSharedMemorySize, SM_BYTES);

    prep_all<<<(2 * BB * 128 + HID * 128) / 256, 256>>>(dataX, dataY, W1, b1, W2);

    dim3 grid(BB / 8, BB / 16);   // 64 x-tiles x 32 y-tiles
    mlp_mma_kernel<<<grid, 256, SM_BYTES>>>(b2, W3, b3);

    final_kernel<<<1, BB>>>(out);
}